// round 12
// baseline (speedup 1.0000x reference)
#include <cuda_runtime.h>
#include <cuda_bf16.h>
#include <stdint.h>
#include <math_constants.h>

// Problem shape (fixed)
#define D   512
#define BQ  4096
#define KA  32768
#define H_ELEMS (BQ * D)
#define A_ELEMS (KA * D)

// GEMM tiling: CTA 128x128, K-tile 64, 3-stage cp.async, 256 threads, 2 CTA/SM
#define BM 128
#define BN 128
#define BK 64
#define NSTG 3
#define NKT (D / BK)                       // 8
#define ROWB 144                           // 128B data + 16B pad per smem row
#define STG_ROWS (BM + BN)                 // 256 (A rows then B rows)
#define STG_BYTES (STG_ROWS * ROWB)        // 36864
#define SMEM_TOTAL (NSTG * STG_BYTES)      // 110592 -> 2 CTAs/SM
#define WTILES (KA / 32)                   // 1024 (32-col tiles per row)
#define MARGIN 0.15f

// Device scratch
__device__ __nv_bfloat16 g_Hb[H_ELEMS];
__device__ __nv_bfloat16 g_Ab[A_ELEMS];    // A scaled by 1/||a||
__device__ float g_inv_a[KA];
__device__ uint4 g_cand[(size_t)BQ * WTILES];  // {s1,i1,s2,i2} per (row, 32-col tile)

// ---------------------------------------------------------------------------
__global__ void k_prep_h(const float* __restrict__ H) {
    int i = blockIdx.x * blockDim.x + threadIdx.x;
    float2 v = ((const float2*)H)[i];
    __nv_bfloat162 p = __floats2bfloat162_rn(v.x, v.y);
    ((unsigned*)g_Hb)[i] = *(unsigned*)&p;
}

__global__ void k_prep_a(const float* __restrict__ A) {
    int gw = (blockIdx.x * blockDim.x + threadIdx.x) >> 5;
    int lane = threadIdx.x & 31;
    if (gw >= KA) return;
    const float4* row = (const float4*)(A + (size_t)gw * D);
    float4 v[4]; float s = 0.f;
#pragma unroll
    for (int i = 0; i < 4; i++) {
        v[i] = row[lane + 32 * i];
        s += v[i].x * v[i].x + v[i].y * v[i].y + v[i].z * v[i].z + v[i].w * v[i].w;
    }
#pragma unroll
    for (int o = 16; o; o >>= 1) s += __shfl_xor_sync(0xffffffffu, s, o);
    float inv = 1.0f / fmaxf(sqrtf(s), 1e-8f);
    if (lane == 0) g_inv_a[gw] = inv;
    unsigned* dst = (unsigned*)(g_Ab + (size_t)gw * D);
#pragma unroll
    for (int i = 0; i < 4; i++) {
        __nv_bfloat162 p0 = __floats2bfloat162_rn(v[i].x * inv, v[i].y * inv);
        __nv_bfloat162 p1 = __floats2bfloat162_rn(v[i].z * inv, v[i].w * inv);
        int e = lane + 32 * i;
        dst[2 * e]     = *(unsigned*)&p0;
        dst[2 * e + 1] = *(unsigned*)&p1;
    }
}

// ---------------------------------------------------------------------------
#define MMA16816(d, a0, a1, a2, a3, b0, b1) asm volatile( \
    "mma.sync.aligned.m16n8k16.row.col.f32.bf16.bf16.f32 " \
    "{%0,%1,%2,%3}, {%4,%5,%6,%7}, {%8,%9}, {%0,%1,%2,%3};" \
    : "+f"(d[0]), "+f"(d[1]), "+f"(d[2]), "+f"(d[3]) \
    : "r"(a0), "r"(a1), "r"(a2), "r"(a3), "r"(b0), "r"(b1))

__global__ __launch_bounds__(256, 2) void k_gemm_bf16() {
    extern __shared__ char smem[];
    unsigned sb = (unsigned)__cvta_generic_to_shared(smem);

    int t = threadIdx.x, lane = t & 31, warp = t >> 5;
    int wm = warp >> 2, wn = warp & 3;         // 2 x 4 warp grid; warp tile 64(m) x 32(n)
    int m0 = blockIdx.y * BM, n0 = blockIdx.x * BN;
    int lrow = lane >> 2, lcol = lane & 3;

    // Loader: thread t fills smem row t (128B = 8 x 16B cp.async chunks).
    // Global source: rows 0..127 -> H tile, rows 128..255 -> A tile.
    const char* gsrc = (t < BM)
        ? (const char*)(g_Hb + (size_t)(m0 + t) * D)
        : (const char*)(g_Ab + (size_t)(n0 + (t - BM)) * D);
    unsigned drow = sb + (unsigned)t * ROWB;

    // ldmatrix byte offsets within a stage (144B rows -> distinct banks per 8-row phase)
    unsigned offA = (unsigned)(wm * 64 + (lane & 15)) * ROWB + ((lane >> 4) * 16);
    unsigned offB = (unsigned)(BM + wn * 32 + (lane & 7) + ((lane >> 4) * 8)) * ROWB
                    + (((lane >> 3) & 1) * 16);

    float acc[4][4][4];
#pragma unroll
    for (int mi = 0; mi < 4; mi++)
#pragma unroll
        for (int ni = 0; ni < 4; ni++)
#pragma unroll
            for (int c = 0; c < 4; c++) acc[mi][ni][c] = 0.f;

    auto issue = [&](int kt) {
        unsigned stg = drow + (unsigned)(kt % NSTG) * STG_BYTES;
        const char* src = gsrc + kt * (BK * 2);
#pragma unroll
        for (int seg = 0; seg < 8; seg++)
            asm volatile("cp.async.cg.shared.global [%0], [%1], 16;"
                         :: "r"(stg + seg * 16), "l"(src + seg * 16) : "memory");
        asm volatile("cp.async.commit_group;" ::: "memory");
    };

    // Prologue: 2 stages in flight
    issue(0); issue(1);

    for (int kt = 0; kt < NKT; kt++) {
        asm volatile("cp.async.wait_group 1;" ::: "memory");
        __syncthreads();
        if (kt + NSTG - 1 < NKT) issue(kt + NSTG - 1);
        else asm volatile("cp.async.commit_group;" ::: "memory");  // keep group count

        unsigned stg = sb + (unsigned)(kt % NSTG) * STG_BYTES;
#pragma unroll
        for (int kf = 0; kf < 4; kf++) {               // 4 x K16 per K64 tile
            unsigned a[4][4], b[2][4];
#pragma unroll
            for (int mi = 0; mi < 4; mi++) {
                unsigned ad = stg + offA + (unsigned)(mi * 16 * ROWB) + kf * 32;
                asm volatile("ldmatrix.sync.aligned.m8n8.x4.shared.b16 {%0,%1,%2,%3}, [%4];"
                             : "=r"(a[mi][0]), "=r"(a[mi][1]), "=r"(a[mi][2]), "=r"(a[mi][3])
                             : "r"(ad));
            }
#pragma unroll
            for (int nj = 0; nj < 2; nj++) {           // each x4 covers 2 n8-tiles
                unsigned bd = stg + offB + (unsigned)(nj * 16 * ROWB) + kf * 32;
                asm volatile("ldmatrix.sync.aligned.m8n8.x4.shared.b16 {%0,%1,%2,%3}, [%4];"
                             : "=r"(b[nj][0]), "=r"(b[nj][1]), "=r"(b[nj][2]), "=r"(b[nj][3])
                             : "r"(bd));
            }
#pragma unroll
            for (int mi = 0; mi < 4; mi++)
#pragma unroll
                for (int nj = 0; nj < 2; nj++) {
                    MMA16816(acc[mi][2 * nj],     a[mi][0], a[mi][1], a[mi][2], a[mi][3],
                             b[nj][0], b[nj][1]);
                    MMA16816(acc[mi][2 * nj + 1], a[mi][0], a[mi][1], a[mi][2], a[mi][3],
                             b[nj][2], b[nj][3]);
                }
        }
    }

    // Epilogue (proven R7 code): per (row, 32-col warp tile) top-2, 4-lane merge.
#pragma unroll
    for (int mi = 0; mi < 4; mi++)
#pragma unroll
        for (int h = 0; h < 2; h++) {
            float s1 = -CUDART_INF_F, s2 = -CUDART_INF_F;
            unsigned i1 = 0, i2 = 0;
#pragma unroll
            for (int ni = 0; ni < 4; ni++)
#pragma unroll
                for (int c = 0; c < 2; c++) {
                    float v = acc[mi][ni][h * 2 + c];
                    unsigned n = (unsigned)(n0 + wn * 32 + ni * 8 + lcol * 2 + c);
                    if (v > s1) { s2 = s1; i2 = i1; s1 = v; i1 = n; }
                    else if (v > s2) { s2 = v; i2 = n; }
                }
#pragma unroll
            for (int off = 1; off <= 2; off <<= 1) {
                float t1 = __shfl_xor_sync(0xffffffffu, s1, off);
                unsigned j1 = __shfl_xor_sync(0xffffffffu, i1, off);
                float t2 = __shfl_xor_sync(0xffffffffu, s2, off);
                unsigned j2 = __shfl_xor_sync(0xffffffffu, i2, off);
                if (t1 > s1) {
                    float os = s1; unsigned oi = i1;
                    s1 = t1; i1 = j1;
                    if (t2 > os) { s2 = t2; i2 = j2; } else { s2 = os; i2 = oi; }
                } else if (t1 > s2) { s2 = t1; i2 = j1; }
            }
            if (lcol == 0) {
                int rg = m0 + wm * 64 + mi * 16 + lrow + h * 8;
                g_cand[(size_t)rg * WTILES + (size_t)(blockIdx.x * 4 + wn)] =
                    make_uint4(__float_as_uint(s1), i1, __float_as_uint(s2), i2);
            }
        }
}

// ---------------------------------------------------------------------------
// Per row: approx max over 2048 candidates, fp32-rescore within MARGIN,
// exact argmax (first-index tie-break). One warp per row. (Proven code.)
// ---------------------------------------------------------------------------
__global__ void k_select(const float* __restrict__ H, const float* __restrict__ A,
                         float* __restrict__ out) {
    int r = (blockIdx.x * blockDim.x + threadIdx.x) >> 5;
    int lane = threadIdx.x & 31;
    if (r >= BQ) return;
    const uint2* cand = (const uint2*)(g_cand + (size_t)r * WTILES);  // 2048 entries

    float mx = -CUDART_INF_F;
    for (int j = lane; j < WTILES * 2; j += 32)
        mx = fmaxf(mx, __uint_as_float(cand[j].x));
#pragma unroll
    for (int o = 16; o; o >>= 1) mx = fmaxf(mx, __shfl_xor_sync(0xffffffffu, mx, o));
    float thr = mx - MARGIN;

    const float4* h4 = (const float4*)(H + (size_t)r * D);
    float4 hv[4];
#pragma unroll
    for (int i = 0; i < 4; i++) hv[i] = h4[lane + 32 * i];

    unsigned long long best = 0ull;
    for (int j0 = 0; j0 < WTILES * 2; j0 += 32) {
        uint2 c = cand[j0 + lane];
        unsigned m = __ballot_sync(0xffffffffu, __uint_as_float(c.x) >= thr);
        while (m) {
            int src = __ffs(m) - 1; m &= m - 1;
            unsigned idx = __shfl_sync(0xffffffffu, c.y, src);
            const float4* a4 = (const float4*)(A + (size_t)idx * D);
            float p = 0.f;
#pragma unroll
            for (int i = 0; i < 4; i++) {
                float4 av = a4[lane + 32 * i];
                p += hv[i].x * av.x + hv[i].y * av.y + hv[i].z * av.z + hv[i].w * av.w;
            }
#pragma unroll
            for (int o = 16; o; o >>= 1) p += __shfl_xor_sync(0xffffffffu, p, o);
            float s = p * g_inv_a[idx];
            unsigned u = __float_as_uint(s);
            u = (u & 0x80000000u) ? ~u : (u | 0x80000000u);
            unsigned long long key =
                ((unsigned long long)u << 32) | (unsigned long long)(0xFFFFFFFFu - idx);
            if (key > best) best = key;
        }
    }
    if (lane == 0)
        out[r] = (float)(0xFFFFFFFFu - (unsigned)(best & 0xFFFFFFFFull));
}

// ---------------------------------------------------------------------------
extern "C" void kernel_launch(void* const* d_in, const int* in_sizes, int n_in,
                              void* d_out, int out_size) {
    const float* H = (const float*)d_in[0];
    const float* A = (const float*)d_in[1];
    if (n_in >= 2 && in_sizes[0] == A_ELEMS) {   // bind by size
        H = (const float*)d_in[1];
        A = (const float*)d_in[0];
    }

    k_prep_h<<<H_ELEMS / 2 / 256, 256>>>(H);
    k_prep_a<<<KA / 8, 256>>>(A);

    cudaFuncSetAttribute(k_gemm_bf16, cudaFuncAttributeMaxDynamicSharedMemorySize, SMEM_TOTAL);
    dim3 grid(KA / BN, BQ / BM);                 // 256 x 32 = 8192 CTAs
    k_gemm_bf16<<<grid, 256, SMEM_TOTAL>>>();

    k_select<<<BQ / 8, 256>>>(H, A, (float*)d_out);
}